// round 9
// baseline (speedup 1.0000x reference)
#include <cuda_runtime.h>
#include <cuda_bf16.h>
#include <math.h>
#include <stdint.h>

typedef unsigned long long u64;

#define BDIM 128
#define LDIM 128
#define NNEI 6
#define FAA 39
#define FBB 10
#define FC 49
#define DD 200
#define D2 400
#define D3 600
#define RR 3
#define TTI 2
#define MBOND 256
#define NEGV -9e8f
#define NATOM (BDIM*LDIM)    /* 16384 */
#define NROWN (NATOM*NNEI)   /* 98304 */
#define KPAD 64
#define KP 224               /* padded K for weight buffers */
#define KPW (KP/2)           /* packed pairs per row = 112 */

// ---------------- device scratch (static, no allocation) ----------------
__device__ float g_atomfeat[NATOM*DD];   // h ping
__device__ float g_hB[NATOM*DD];         // h pong
__device__ float g_atompad[NATOM*KPAD];
__device__ float g_cur[NATOM*DD];
__device__ float g_ctx[NATOM*DD];
__device__ float g_wsum[NATOM*DD];
__device__ float g_wtot[NATOM];
__device__ float g_concat[NROWN*KPAD];
__device__ float g_nei0[NROWN*DD];
__device__ float g_s2[NATOM];
__device__ float g_mol[BDIM*DD];
__device__ float g_mol2[BDIM*DD];
__device__ float g_actmol[BDIM*DD];
__device__ float g_mwsum[BDIM*DD];
__device__ float g_mwtot[BDIM];
__device__ float g_mctx[BDIM*DD];
// packed bf16-pair weights (hi and lo planes)
__device__ uint32_t g_WT_atom_h[200*KPW],  g_WT_atom_l[200*KPW];
__device__ uint32_t g_WT_nei_h[200*KPW],   g_WT_nei_l[200*KPW];
__device__ uint32_t g_WT_att_h[3*200*KPW], g_WT_att_l[3*200*KPW];
__device__ uint32_t g_WT_molatt_h[200*KPW],g_WT_molatt_l[200*KPW];
// GRU weights: gate-interleaved rows n' = dblock*24 + gate*8 + dlow
__device__ uint32_t g_Wih_h[3*600*KPW],    g_Wih_l[3*600*KPW];
__device__ uint32_t g_Whh_h[3*600*KPW],    g_Whh_l[3*600*KPW];
__device__ uint32_t g_mWih_h[600*KPW],     g_mWih_l[600*KPW];
__device__ uint32_t g_mWhh_h[600*KPW],     g_mWhh_l[600*KPW];

// ---------------- helpers ----------------
__device__ __forceinline__ float warpsum(float v) {
    #pragma unroll
    for (int o = 16; o > 0; o >>= 1) v += __shfl_down_sync(0xffffffffu, v, o);
    return v;
}
__device__ __forceinline__ float lrelu(float x) { return x > 0.f ? x : 0.01f * x; }
__device__ __forceinline__ float eluf(float x)  { return x > 0.f ? x : expm1f(x); }
__device__ __forceinline__ float sigm(float x)  { return 1.f / (1.f + expf(-x)); }

__device__ __forceinline__ void split_bf16(float x, __nv_bfloat16& h, __nv_bfloat16& l) {
    h = __float2bfloat16_rn(x);
    l = __float2bfloat16_rn(x - __bfloat162float(h));
}
__device__ __forceinline__ uint32_t pack2(__nv_bfloat16 a, __nv_bfloat16 b) {
    __nv_bfloat162 p = __halves2bfloat162(a, b);
    return *reinterpret_cast<uint32_t*>(&p);
}

#define MMAB(c, a, b) \
    asm volatile("mma.sync.aligned.m16n8k16.row.col.f32.bf16.bf16.f32 " \
        "{%0,%1,%2,%3}, {%4,%5,%6,%7}, {%8,%9}, {%0,%1,%2,%3};" \
        : "+f"((c)[0]), "+f"((c)[1]), "+f"((c)[2]), "+f"((c)[3]) \
        : "r"((a)[0]), "r"((a)[1]), "r"((a)[2]), "r"((a)[3]), \
          "r"((b)[0]), "r"((b)[1]))

// =====================================================================
// Split-bf16 tensor GEMM (same as validated R8 kernel)
// =====================================================================
__global__ __launch_bounds__(256) void bfgemm_kernel(
    const float* __restrict__ A, int lda, int K,
    const uint32_t* __restrict__ WTh, const uint32_t* __restrict__ WTl,
    const float* __restrict__ bias,
    const float* __restrict__ rowscale,
    float* __restrict__ C, int M, int Ntot, int act)
{
    __shared__ uint32_t APh[8][132], APl[8][132];
    __shared__ uint32_t BPh[8][72],  BPl[8][72];

    const int tid = threadIdx.x;
    const int wid = tid >> 5;
    const int lane = tid & 31;
    const int gid = lane >> 2;
    const int tg = lane & 3;
    const int bm0 = blockIdx.x * 128;
    const int bn0 = blockIdx.y * 64;
    const int wm = (wid & 3) * 32;
    const int wn = (wid >> 2) * 32;

    float c[2][4][4];
    #pragma unroll
    for (int mt = 0; mt < 2; mt++)
        #pragma unroll
        for (int nt = 0; nt < 4; nt++)
            #pragma unroll
            for (int q = 0; q < 4; q++) c[mt][nt][q] = 0.f;

    const int nch = (K + 15) >> 4;
    for (int chn = 0; chn < nch; chn++) {
        const int k0 = chn << 4;
        #pragma unroll
        for (int it = 0; it < 2; it++) {
            int i = tid + it * 256;
            int r = i >> 2, c4 = (i & 3) << 2;
            int k = k0 + c4;
            float4 v = make_float4(0.f, 0.f, 0.f, 0.f);
            if (k < K) v = *reinterpret_cast<const float4*>(A + (size_t)(bm0 + r) * lda + k);
            __nv_bfloat16 h0, l0, h1, l1, h2, l2, h3, l3;
            split_bf16(v.x, h0, l0); split_bf16(v.y, h1, l1);
            split_bf16(v.z, h2, l2); split_bf16(v.w, h3, l3);
            int kp = c4 >> 1;
            APh[kp][r]     = pack2(h0, h1);
            APh[kp + 1][r] = pack2(h2, h3);
            APl[kp][r]     = pack2(l0, l1);
            APl[kp + 1][r] = pack2(l2, l3);
        }
        {
            int r = tid >> 2, kp2 = (tid & 3) << 1;
            int n = bn0 + r;
            uint2 vh = make_uint2(0u, 0u), vl = make_uint2(0u, 0u);
            if (n < Ntot) {
                size_t off = (size_t)n * KPW + (k0 >> 1) + kp2;
                vh = *reinterpret_cast<const uint2*>(WTh + off);
                vl = *reinterpret_cast<const uint2*>(WTl + off);
            }
            BPh[kp2][r] = vh.x; BPh[kp2 + 1][r] = vh.y;
            BPl[kp2][r] = vl.x; BPl[kp2 + 1][r] = vl.y;
        }
        __syncthreads();

        uint32_t ah[2][4], al[2][4];
        #pragma unroll
        for (int mt = 0; mt < 2; mt++) {
            int mr = wm + mt * 16;
            ah[mt][0] = APh[tg][mr + gid];
            ah[mt][1] = APh[tg][mr + gid + 8];
            ah[mt][2] = APh[tg + 4][mr + gid];
            ah[mt][3] = APh[tg + 4][mr + gid + 8];
            al[mt][0] = APl[tg][mr + gid];
            al[mt][1] = APl[tg][mr + gid + 8];
            al[mt][2] = APl[tg + 4][mr + gid];
            al[mt][3] = APl[tg + 4][mr + gid + 8];
        }
        uint32_t bh[4][2], bl[4][2];
        #pragma unroll
        for (int nt = 0; nt < 4; nt++) {
            int nc = wn + nt * 8 + gid;
            bh[nt][0] = BPh[tg][nc];
            bh[nt][1] = BPh[tg + 4][nc];
            bl[nt][0] = BPl[tg][nc];
            bl[nt][1] = BPl[tg + 4][nc];
        }
        #pragma unroll
        for (int mt = 0; mt < 2; mt++)
            #pragma unroll
            for (int nt = 0; nt < 4; nt++) {
                MMAB(c[mt][nt], ah[mt], bh[nt]);
                MMAB(c[mt][nt], ah[mt], bl[nt]);
                MMAB(c[mt][nt], al[mt], bh[nt]);
            }
        __syncthreads();
    }

    #pragma unroll
    for (int mt = 0; mt < 2; mt++) {
        #pragma unroll
        for (int half = 0; half < 2; half++) {
            int m = bm0 + wm + mt * 16 + gid + half * 8;
            float rs = rowscale ? rowscale[m] : 1.f;
            float* crow = C + (size_t)m * Ntot;
            #pragma unroll
            for (int nt = 0; nt < 4; nt++) {
                int n = bn0 + wn + nt * 8 + 2 * tg;
                float v0 = c[mt][nt][half * 2 + 0];
                float v1 = c[mt][nt][half * 2 + 1];
                if (n < Ntot) {
                    float v = v0 + rs * (bias ? bias[n] : 0.f);
                    if (act == 1) v = lrelu(v);
                    else if (act == 2) v = eluf(v);
                    crow[n] = v;
                }
                if (n + 1 < Ntot) {
                    float v = v1 + rs * (bias ? bias[n + 1] : 0.f);
                    if (act == 1) v = lrelu(v);
                    else if (act == 2) v = eluf(v);
                    crow[n + 1] = v;
                }
            }
        }
    }
}

// =====================================================================
// Fused GRU GEMM: computes gi = X@Wih^T, gh = Hin@Whh^T for one 24-col
// gate-interleaved tile (all 3 gates of 8 d values) and applies the GRU
// nonlinearity in the epilogue. Writes hOut and actOut (relu).
// BM=128 (8 warps x 16 rows), BN=24 (3 gate tiles of 8). grid=(M/128, 25).
// Wih/Whh rows rearranged: n' = dblock*24 + gate*8 + dlow.
// =====================================================================
__global__ __launch_bounds__(256) void gru_gemm_kernel(
    const float* __restrict__ X, const float* __restrict__ Hin, int M,
    const uint32_t* __restrict__ Wih_h, const uint32_t* __restrict__ Wih_l,
    const uint32_t* __restrict__ Whh_h, const uint32_t* __restrict__ Whh_l,
    const float* __restrict__ bih, const float* __restrict__ bhh,
    float* __restrict__ hOut, float* __restrict__ actOut)
{
    __shared__ uint32_t XPh[8][132], XPl[8][132], HPh[8][132], HPl[8][132];
    __shared__ uint32_t BIh[8][24], BIl[8][24], BHh[8][24], BHl[8][24];

    const int tid = threadIdx.x;
    const int wid = tid >> 5;
    const int lane = tid & 31;
    const int gid = lane >> 2;
    const int tg = lane & 3;
    const int bm0 = blockIdx.x * 128;
    const int dblock = blockIdx.y;          // 0..24
    const int nrow0 = dblock * 24;
    const int wm = wid * 16;

    float ci[3][4], chh[3][4];
    #pragma unroll
    for (int nt = 0; nt < 3; nt++)
        #pragma unroll
        for (int q = 0; q < 4; q++) { ci[nt][q] = 0.f; chh[nt][q] = 0.f; }

    const int nch = 13;  // K=200 -> 13 chunks of 16
    for (int chn = 0; chn < nch; chn++) {
        const int k0 = chn << 4;
        // stage X and Hin tiles: 128 rows x 16 k each (512 float4 per matrix)
        #pragma unroll
        for (int it = 0; it < 2; it++) {
            int i = tid + it * 256;
            int r = i >> 2, c4 = (i & 3) << 2;
            int k = k0 + c4;
            int gr = bm0 + r;
            bool ok = (gr < M) && (k < DD);
            float4 vx = make_float4(0.f, 0.f, 0.f, 0.f);
            float4 vh = make_float4(0.f, 0.f, 0.f, 0.f);
            if (ok) {
                vx = *reinterpret_cast<const float4*>(X + (size_t)gr * DD + k);
                vh = *reinterpret_cast<const float4*>(Hin + (size_t)gr * DD + k);
            }
            int kp = c4 >> 1;
            __nv_bfloat16 h0, l0, h1, l1, h2, l2, h3, l3;
            split_bf16(vx.x, h0, l0); split_bf16(vx.y, h1, l1);
            split_bf16(vx.z, h2, l2); split_bf16(vx.w, h3, l3);
            XPh[kp][r] = pack2(h0, h1); XPh[kp + 1][r] = pack2(h2, h3);
            XPl[kp][r] = pack2(l0, l1); XPl[kp + 1][r] = pack2(l2, l3);
            split_bf16(vh.x, h0, l0); split_bf16(vh.y, h1, l1);
            split_bf16(vh.z, h2, l2); split_bf16(vh.w, h3, l3);
            HPh[kp][r] = pack2(h0, h1); HPh[kp + 1][r] = pack2(h2, h3);
            HPl[kp][r] = pack2(l0, l1); HPl[kp + 1][r] = pack2(l2, l3);
        }
        // stage B tiles: 24 rows x 8 kpairs, 4 planes
        if (tid < 192) {
            int r = tid >> 3, kp = tid & 7;
            size_t off = (size_t)(nrow0 + r) * KPW + (k0 >> 1) + kp;
            BIh[kp][r] = Wih_h[off];
            BIl[kp][r] = Wih_l[off];
            BHh[kp][r] = Whh_h[off];
            BHl[kp][r] = Whh_l[off];
        }
        __syncthreads();

        uint32_t xh[4], xl[4], hh[4], hl[4];
        xh[0] = XPh[tg][wm + gid];     xh[1] = XPh[tg][wm + gid + 8];
        xh[2] = XPh[tg + 4][wm + gid]; xh[3] = XPh[tg + 4][wm + gid + 8];
        xl[0] = XPl[tg][wm + gid];     xl[1] = XPl[tg][wm + gid + 8];
        xl[2] = XPl[tg + 4][wm + gid]; xl[3] = XPl[tg + 4][wm + gid + 8];
        hh[0] = HPh[tg][wm + gid];     hh[1] = HPh[tg][wm + gid + 8];
        hh[2] = HPh[tg + 4][wm + gid]; hh[3] = HPh[tg + 4][wm + gid + 8];
        hl[0] = HPl[tg][wm + gid];     hl[1] = HPl[tg][wm + gid + 8];
        hl[2] = HPl[tg + 4][wm + gid]; hl[3] = HPl[tg + 4][wm + gid + 8];

        #pragma unroll
        for (int nt = 0; nt < 3; nt++) {
            int nc = nt * 8 + gid;
            uint32_t bi_h[2] = { BIh[tg][nc], BIh[tg + 4][nc] };
            uint32_t bi_l[2] = { BIl[tg][nc], BIl[tg + 4][nc] };
            uint32_t bh_h[2] = { BHh[tg][nc], BHh[tg + 4][nc] };
            uint32_t bh_l[2] = { BHl[tg][nc], BHl[tg + 4][nc] };
            MMAB(ci[nt], xh, bi_h);
            MMAB(ci[nt], xh, bi_l);
            MMAB(ci[nt], xl, bi_h);
            MMAB(chh[nt], hh, bh_h);
            MMAB(chh[nt], hh, bh_l);
            MMAB(chh[nt], hl, bh_h);
        }
        __syncthreads();
    }

    // GRU epilogue: nt0=r gate, nt1=z gate, nt2=n gate; d = dblock*8 + 2tg + q
    #pragma unroll
    for (int half = 0; half < 2; half++) {
        int m = bm0 + wm + gid + half * 8;
        if (m >= M) continue;
        #pragma unroll
        for (int q = 0; q < 2; q++) {
            int d = dblock * 8 + 2 * tg + q;
            int ix = half * 2 + q;
            float ir = ci[0][ix] + bih[d];
            float hr = chh[0][ix] + bhh[d];
            float iz = ci[1][ix] + bih[DD + d];
            float hz = chh[1][ix] + bhh[DD + d];
            float inn = ci[2][ix] + bih[2 * DD + d];
            float hnv = chh[2][ix] + bhh[2 * DD + d];
            float r = sigm(ir + hr);
            float z = sigm(iz + hz);
            float nv = tanhf(inn + r * hnv);
            float hv = Hin[(size_t)m * DD + d];
            float hn = (1.f - z) * nv + z * hv;
            hOut[(size_t)m * DD + d] = hn;
            actOut[(size_t)m * DD + d] = hn > 0.f ? hn : 0.f;
        }
    }
}

// ---------------- weight prep: [NT,K] row-major -> packed hi/lo [NT,KPW] ----------------
__global__ void prep_pad_bf(const float* __restrict__ in,
                            uint32_t* __restrict__ outh, uint32_t* __restrict__ outl,
                            int NT, int K)
{
    int i = blockIdx.x * 256 + threadIdx.x;
    if (i >= NT * KPW) return;
    int n = i / KPW, kp = i - n * KPW;
    int k = kp << 1;
    float x0 = (k < K) ? in[(size_t)n * K + k] : 0.f;
    float x1 = (k + 1 < K) ? in[(size_t)n * K + k + 1] : 0.f;
    __nv_bfloat16 h0, l0, h1, l1;
    split_bf16(x0, h0, l0); split_bf16(x1, h1, l1);
    outh[i] = pack2(h0, h1);
    outl[i] = pack2(l0, l1);
}

// ---------------- weight prep: GRU [R,3D,D] -> gate-interleaved packed [R,600,KPW] ----------------
__global__ void prep_gru_bf(const float* __restrict__ in,
                            uint32_t* __restrict__ outh, uint32_t* __restrict__ outl,
                            int R)
{
    int i = blockIdx.x * 256 + threadIdx.x;
    if (i >= R * D3 * KPW) return;
    int kp = i % KPW;
    int rn = i / KPW;
    int np = rn % D3;
    int r = rn / D3;
    int dblk = np / 24, rem = np % 24;
    int gate = rem >> 3, dlow = rem & 7;
    int orow = gate * DD + dblk * 8 + dlow;
    int k = kp << 1;
    float x0 = (k < DD) ? in[((size_t)r * D3 + orow) * DD + k] : 0.f;
    float x1 = (k + 1 < DD) ? in[((size_t)r * D3 + orow) * DD + k + 1] : 0.f;
    __nv_bfloat16 h0, l0, h1, l1;
    split_bf16(x0, h0, l0); split_bf16(x1, h1, l1);
    outh[i] = pack2(h0, h1);
    outl[i] = pack2(l0, l1);
}

// ---------------- weight prep: [R,K,N] -> packed hi/lo [R,N,KPW] ----------------
__global__ void prep_trans_bf(const float* __restrict__ in,
                              uint32_t* __restrict__ outh, uint32_t* __restrict__ outl,
                              int R, int K, int N)
{
    int i = blockIdx.x * 256 + threadIdx.x;
    if (i >= R * N * KPW) return;
    int kp = i % KPW;
    int rn = i / KPW;
    int n = rn % N;
    int r = rn / N;
    int k = kp << 1;
    float x0 = (k < K) ? in[((size_t)r * K + k) * N + n] : 0.f;
    float x1 = (k + 1 < K) ? in[((size_t)r * K + k + 1) * N + n] : 0.f;
    __nv_bfloat16 h0, l0, h1, l1;
    split_bf16(x0, h0, l0); split_bf16(x1, h1, l1);
    outh[i] = pack2(h0, h1);
    outl[i] = pack2(l0, l1);
}

// ---------------- pad atom_list [NATOM,39] -> [NATOM,64] ----------------
__global__ void pad_atom_kernel(const float* __restrict__ atom_list, float* __restrict__ out)
{
    int i = blockIdx.x * blockDim.x + threadIdx.x;
    if (i >= NATOM * KPAD) return;
    int row = i >> 6;
    int f = i & 63;
    out[i] = (f < FAA) ? atom_list[row * FAA + f] : 0.f;
}

// ---------------- build concat(atom_nei, bond_nei) [NROWN, 64] padded ----------------
__global__ void build_concat(const float* __restrict__ atom_list,
                             const float* __restrict__ bond_list,
                             const int* __restrict__ adeg,
                             const int* __restrict__ bdeg,
                             float* __restrict__ out)
{
    int i = blockIdx.x * blockDim.x + threadIdx.x;
    if (i >= NROWN * KPAD) return;
    int row = i >> 6;
    int f = i & 63;
    int b = row / (LDIM * NNEI);
    float v = 0.f;
    if (f < FAA) {
        int a = adeg[row];
        v = atom_list[((size_t)b * LDIM + a) * FAA + f];
    } else if (f < FC) {
        int bd = bdeg[row];
        v = bond_list[((size_t)b * MBOND + bd) * FBB + (f - FAA)];
    }
    out[i] = v;
}

// ---------------- attention: softmax weights + weighted neighbor sum ----------------
__global__ void ctx_kernel(const float* __restrict__ cur,
                           const float* __restrict__ neiBuf,
                           const int* __restrict__ adeg,
                           const float* __restrict__ Wal,
                           const float* __restrict__ bal,
                           float* __restrict__ wsum,
                           float* __restrict__ wtot,
                           int firstRound)
{
    const int atom = blockIdx.x;
    const int b = atom / LDIM;
    const int tid = threadIdx.x;
    const int lane = tid & 31;

    __shared__ float curS[DD];
    __shared__ float neiS[NNEI][DD];
    __shared__ float red[NNEI + 1];
    __shared__ int idxS[NNEI];

    if (tid <= NNEI) red[tid] = 0.f;
    if (tid < NNEI) idxS[tid] = adeg[atom * NNEI + tid];
    for (int d = tid; d < DD; d += 256) curS[d] = cur[(size_t)atom * DD + d];
    __syncthreads();

    #pragma unroll
    for (int n = 0; n < NNEI; n++) {
        const float* src = firstRound ? (neiBuf + ((size_t)atom * NNEI + n) * DD)
                                      : (cur + ((size_t)(b * LDIM + idxS[n])) * DD);
        for (int d = tid; d < DD; d += 256) neiS[n][d] = src[d];
    }
    __syncthreads();

    float p[NNEI + 1];
    #pragma unroll
    for (int n = 0; n <= NNEI; n++) p[n] = 0.f;
    for (int d = tid; d < DD; d += 256) {
        float a1 = Wal[d];
        float a2 = Wal[DD + d];
        p[NNEI] += a1 * curS[d];
        #pragma unroll
        for (int n = 0; n < NNEI; n++) p[n] += a2 * neiS[n][d];
    }
    #pragma unroll
    for (int n = 0; n <= NNEI; n++) {
        float s = warpsum(p[n]);
        if (lane == 0) atomicAdd(&red[n], s);
    }
    __syncthreads();

    float dtop = red[NNEI];
    float bb = bal[0];
    float sc[NNEI];
    float msk[NNEI];
    float mx = -1e30f;
    #pragma unroll
    for (int n = 0; n < NNEI; n++) {
        float a = lrelu(dtop + red[n] + bb);
        bool pad = (idxS[n] == LDIM - 1);
        msk[n] = pad ? 0.f : 1.f;
        a += pad ? NEGV : 0.f;
        sc[n] = a;
        mx = fmaxf(mx, a);
    }
    float sum = 0.f;
    float w[NNEI];
    #pragma unroll
    for (int n = 0; n < NNEI; n++) { w[n] = expf(sc[n] - mx); sum += w[n]; }
    float inv = 1.f / sum;
    float wt = 0.f;
    #pragma unroll
    for (int n = 0; n < NNEI; n++) { w[n] = w[n] * inv * msk[n]; wt += w[n]; }

    for (int d = tid; d < DD; d += 256) {
        float s = 0.f;
        #pragma unroll
        for (int n = 0; n < NNEI; n++) s += w[n] * neiS[n][d];
        wsum[(size_t)atom * DD + d] = s;
    }
    if (tid == 0) wtot[atom] = wt;
}

// ---------------- mol prep: masked sum + per-atom s2 dot ----------------
__global__ void molprep_kernel(const float* __restrict__ cur, const float* __restrict__ amask,
                               const float* __restrict__ Wma,
                               float* __restrict__ mol, float* __restrict__ actmol,
                               float* __restrict__ s2)
{
    int b = blockIdx.x;
    int tid = threadIdx.x;
    for (int d = tid; d < DD; d += 256) {
        float s = 0.f;
        for (int l = 0; l < LDIM; l++)
            s += cur[((size_t)b * LDIM + l) * DD + d] * amask[b * LDIM + l];
        mol[b * DD + d] = s;
        actmol[b * DD + d] = s > 0.f ? s : 0.f;
    }
    int w = tid >> 5;
    int lane = tid & 31;
    for (int l = w; l < LDIM; l += 8) {
        float p = 0.f;
        const float* row = cur + ((size_t)b * LDIM + l) * DD;
        for (int d = lane; d < DD; d += 32) p += row[d] * Wma[DD + d];
        p = warpsum(p);
        if (lane == 0) s2[b * LDIM + l] = p;
    }
}

// ---------------- mol attention: weights + weighted atom sum ----------------
__global__ void molctx_kernel(const float* __restrict__ actmol,
                              const float* __restrict__ cur,
                              const float* __restrict__ s2,
                              const float* __restrict__ amask,
                              const float* __restrict__ Wma,
                              const float* __restrict__ bma,
                              float* __restrict__ mwsum,
                              float* __restrict__ mwtot)
{
    int b = blockIdx.x;
    int tid = threadIdx.x;
    int lane = tid & 31;
    __shared__ float redv;
    __shared__ float sc[LDIM];
    __shared__ float wS[LDIM];
    if (tid == 0) redv = 0.f;
    __syncthreads();

    float p = 0.f;
    for (int d = tid; d < DD; d += 256) p += actmol[b * DD + d] * Wma[d];
    p = warpsum(p);
    if (lane == 0) atomicAdd(&redv, p);
    __syncthreads();

    if (tid < LDIM) {
        float a = lrelu(redv + s2[b * LDIM + tid] + bma[0]);
        if (amask[b * LDIM + tid] == 0.f) a += NEGV;
        sc[tid] = a;
    }
    __syncthreads();

    float mx = -1e30f;
    for (int l = 0; l < LDIM; l++) mx = fmaxf(mx, sc[l]);
    float sum = 0.f;
    for (int l = 0; l < LDIM; l++) sum += expf(sc[l] - mx);
    float inv = 1.f / sum;
    if (tid < LDIM) wS[tid] = expf(sc[tid] - mx) * inv * amask[b * LDIM + tid];
    __syncthreads();

    for (int d = tid; d < DD; d += 256) {
        float s = 0.f;
        for (int l = 0; l < LDIM; l++)
            s += wS[l] * cur[((size_t)b * LDIM + l) * DD + d];
        mwsum[b * DD + d] = s;
    }
    if (tid == 0) {
        float wt = 0.f;
        for (int l = 0; l < LDIM; l++) wt += wS[l];
        mwtot[b] = wt;
    }
}

// ---------------- final projection ----------------
__global__ void final_kernel(const float* __restrict__ mol,
                             const float* __restrict__ Wm, const float* __restrict__ bm,
                             const float* __restrict__ Wo, const float* __restrict__ bo,
                             float* __restrict__ out)
{
    int b = blockIdx.x;
    int tid = threadIdx.x;
    int lane = tid & 31;
    __shared__ float featS[D2];
    __shared__ float ws[8];
    for (int j = tid; j < D2; j += 256)
        featS[j] = (j < DD) ? mol[b * DD + j] : (mol[b * DD + j - DD] + (float)(RR - 2));
    __syncthreads();
    float p = 0.f;
    for (int d = tid; d < DD; d += 256) {
        float s = bm[d];
        for (int j = 0; j < D2; j++) s += featS[j] * Wm[j * DD + d];
        p += s * Wo[d];
    }
    p = warpsum(p);
    if (lane == 0) ws[tid >> 5] = p;
    __syncthreads();
    if (tid == 0) {
        float t = 0.f;
        for (int i = 0; i < 8; i++) t += ws[i];
        out[b] = t + bo[0];
    }
}

// ---------------- host-side dispatch ----------------
static void tgemm(const float* A, int lda, int K,
                  const uint32_t* WTh, const uint32_t* WTl,
                  const float* bias, const float* rowscale, float* C,
                  int M, int Ntot, int act)
{
    dim3 g(M / 128, (Ntot + 63) / 64);
    bfgemm_kernel<<<g, 256>>>(A, lda, K, WTh, WTl, bias, rowscale, C, M, Ntot, act);
}

static void grugemm(const float* X, const float* Hin, int M,
                    const uint32_t* Wih_h, const uint32_t* Wih_l,
                    const uint32_t* Whh_h, const uint32_t* Whh_l,
                    const float* bih, const float* bhh,
                    float* hOut, float* actOut)
{
    dim3 g((M + 127) / 128, 25);
    gru_gemm_kernel<<<g, 256>>>(X, Hin, M, Wih_h, Wih_l, Whh_h, Whh_l,
                                bih, bhh, hOut, actOut);
}

extern "C" void kernel_launch(void* const* d_in, const int* in_sizes, int n_in,
                              void* d_out, int out_size)
{
    const float* atom_list   = (const float*)d_in[0];
    const float* bond_list   = (const float*)d_in[1];
    const int*   adeg        = (const int*)d_in[2];
    const int*   bdeg        = (const int*)d_in[3];
    const float* amask       = (const float*)d_in[4];
    const float* W_atom      = (const float*)d_in[5];
    const float* b_atom      = (const float*)d_in[6];
    const float* W_nei       = (const float*)d_in[7];
    const float* b_nei       = (const float*)d_in[8];
    const float* W_align     = (const float*)d_in[9];
    const float* b_align     = (const float*)d_in[10];
    const float* W_attend    = (const float*)d_in[11];
    const float* b_attend    = (const float*)d_in[12];
    const float* Wih         = (const float*)d_in[13];
    const float* Whh         = (const float*)d_in[14];
    const float* bih         = (const float*)d_in[15];
    const float* bhh         = (const float*)d_in[16];
    const float* W_mol_align = (const float*)d_in[17];
    const float* b_mol_align = (const float*)d_in[18];
    const float* W_mol_att   = (const float*)d_in[19];
    const float* b_mol_att   = (const float*)d_in[20];
    const float* mWih        = (const float*)d_in[21];
    const float* mWhh        = (const float*)d_in[22];
    const float* mbih        = (const float*)d_in[23];
    const float* mbhh        = (const float*)d_in[24];
    const float* W_metric    = (const float*)d_in[25];
    const float* b_metric    = (const float*)d_in[26];
    const float* W_out       = (const float*)d_in[27];
    const float* b_out       = (const float*)d_in[28];

    float *atomfeat, *hB, *atompad, *cur, *ctx, *wsum, *wtot, *concat, *nei0;
    float *s2, *mol, *mol2, *actmol, *mwsum, *mwtot, *mctx;
    uint32_t *WT_atom_h, *WT_atom_l, *WT_nei_h, *WT_nei_l, *WT_att_h, *WT_att_l;
    uint32_t *WT_molatt_h, *WT_molatt_l, *Wih_h, *Wih_l, *Whh_h, *Whh_l;
    uint32_t *mWih_h, *mWih_l, *mWhh_h, *mWhh_l;
    cudaGetSymbolAddress((void**)&atomfeat, g_atomfeat);
    cudaGetSymbolAddress((void**)&hB, g_hB);
    cudaGetSymbolAddress((void**)&atompad, g_atompad);
    cudaGetSymbolAddress((void**)&cur, g_cur);
    cudaGetSymbolAddress((void**)&ctx, g_ctx);
    cudaGetSymbolAddress((void**)&wsum, g_wsum);
    cudaGetSymbolAddress((void**)&wtot, g_wtot);
    cudaGetSymbolAddress((void**)&concat, g_concat);
    cudaGetSymbolAddress((void**)&nei0, g_nei0);
    cudaGetSymbolAddress((void**)&s2, g_s2);
    cudaGetSymbolAddress((void**)&mol, g_mol);
    cudaGetSymbolAddress((void**)&mol2, g_mol2);
    cudaGetSymbolAddress((void**)&actmol, g_actmol);
    cudaGetSymbolAddress((void**)&mwsum, g_mwsum);
    cudaGetSymbolAddress((void**)&mwtot, g_mwtot);
    cudaGetSymbolAddress((void**)&mctx, g_mctx);
    cudaGetSymbolAddress((void**)&WT_atom_h, g_WT_atom_h);
    cudaGetSymbolAddress((void**)&WT_atom_l, g_WT_atom_l);
    cudaGetSymbolAddress((void**)&WT_nei_h, g_WT_nei_h);
    cudaGetSymbolAddress((void**)&WT_nei_l, g_WT_nei_l);
    cudaGetSymbolAddress((void**)&WT_att_h, g_WT_att_h);
    cudaGetSymbolAddress((void**)&WT_att_l, g_WT_att_l);
    cudaGetSymbolAddress((void**)&WT_molatt_h, g_WT_molatt_h);
    cudaGetSymbolAddress((void**)&WT_molatt_l, g_WT_molatt_l);
    cudaGetSymbolAddress((void**)&Wih_h, g_Wih_h);
    cudaGetSymbolAddress((void**)&Wih_l, g_Wih_l);
    cudaGetSymbolAddress((void**)&Whh_h, g_Whh_h);
    cudaGetSymbolAddress((void**)&Whh_l, g_Whh_l);
    cudaGetSymbolAddress((void**)&mWih_h, g_mWih_h);
    cudaGetSymbolAddress((void**)&mWih_l, g_mWih_l);
    cudaGetSymbolAddress((void**)&mWhh_h, g_mWhh_h);
    cudaGetSymbolAddress((void**)&mWhh_l, g_mWhh_l);

    // 0) weight prep
    {
        int n;
        n = 3 * D3 * KPW; prep_gru_bf<<<(n + 255) / 256, 256>>>(Wih, Wih_h, Wih_l, 3);
        n = 3 * D3 * KPW; prep_gru_bf<<<(n + 255) / 256, 256>>>(Whh, Whh_h, Whh_l, 3);
        n = D3 * KPW;     prep_gru_bf<<<(n + 255) / 256, 256>>>(mWih, mWih_h, mWih_l, 1);
        n = D3 * KPW;     prep_gru_bf<<<(n + 255) / 256, 256>>>(mWhh, mWhh_h, mWhh_l, 1);
        n = 200 * KPW;  prep_trans_bf<<<(n + 255) / 256, 256>>>(W_atom, WT_atom_h, WT_atom_l, 1, FAA, DD);
        n = 200 * KPW;  prep_trans_bf<<<(n + 255) / 256, 256>>>(W_nei, WT_nei_h, WT_nei_l, 1, FC, DD);
        n = 3 * 200 * KPW; prep_trans_bf<<<(n + 255) / 256, 256>>>(W_attend, WT_att_h, WT_att_l, 3, DD, DD);
        n = 200 * KPW;  prep_trans_bf<<<(n + 255) / 256, 256>>>(W_mol_att, WT_molatt_h, WT_molatt_l, 1, DD, DD);
    }

    // 1) atom_feature = lrelu(atom_list @ W_atom + b_atom)
    pad_atom_kernel<<<(NATOM * KPAD + 255) / 256, 256>>>(atom_list, atompad);
    tgemm(atompad, KPAD, KPAD, WT_atom_h, WT_atom_l, b_atom, nullptr, atomfeat, NATOM, DD, 1);

    // 2) nei0 = lrelu(concat @ W_nei + b_nei)
    build_concat<<<(NROWN * KPAD + 255) / 256, 256>>>(atom_list, bond_list, adeg, bdeg, concat);
    tgemm(concat, KPAD, KPAD, WT_nei_h, WT_nei_l, b_nei, nullptr, nei0, NROWN, DD, 1);

    // 3) atom GRU rounds (h ping-pong: atomfeat -> hB -> atomfeat -> hB)
    float* hbuf[2] = { atomfeat, hB };
    for (int r = 0; r < RR; r++) {
        const float* curp = (r == 0) ? atomfeat : cur;
        float* h_in = hbuf[r & 1];
        float* h_out = hbuf[(r + 1) & 1];
        ctx_kernel<<<NATOM, 256>>>(curp, (r == 0) ? nei0 : nullptr, adeg,
                                   W_align + (size_t)r * D2, b_align + r,
                                   wsum, wtot, (r == 0) ? 1 : 0);
        tgemm(wsum, DD, DD, WT_att_h + (size_t)r * 200 * KPW, WT_att_l + (size_t)r * 200 * KPW,
              b_attend + r * DD, wtot, ctx, NATOM, DD, 2);
        grugemm(ctx, h_in, NATOM,
                Wih_h + (size_t)r * D3 * KPW, Wih_l + (size_t)r * D3 * KPW,
                Whh_h + (size_t)r * D3 * KPW, Whh_l + (size_t)r * D3 * KPW,
                bih + r * D3, bhh + r * D3, h_out, cur);
    }

    // 4) mol phase (mol ping-pong: mol -> mol2 -> mol)
    molprep_kernel<<<BDIM, 256>>>(cur, amask, W_mol_align, mol, actmol, s2);
    float* mbuf[2] = { mol, mol2 };
    for (int t = 0; t < TTI; t++) {
        float* m_in = mbuf[t & 1];
        float* m_out = mbuf[(t + 1) & 1];
        molctx_kernel<<<BDIM, 256>>>(actmol, cur, s2, amask, W_mol_align, b_mol_align,
                                     mwsum, mwtot);
        tgemm(mwsum, DD, DD, WT_molatt_h, WT_molatt_l, b_mol_att, mwtot, mctx, BDIM, DD, 2);
        grugemm(mctx, m_in, BDIM, mWih_h, mWih_l, mWhh_h, mWhh_l,
                mbih, mbhh, m_out, actmol);
    }

    // 5) final projection (TTI even -> result back in g_mol)
    final_kernel<<<BDIM, 256>>>(mol, W_metric, b_metric, W_out, b_out, (float*)d_out);
}